// round 11
// baseline (speedup 1.0000x reference)
#include <cuda_runtime.h>
#include <mma.h>

using namespace nvcuda;

#define BSZ 256
#define SLEN 64
#define HDIM 512
#define H2D 1024
#define VDIM 32000
#define NROWS (BSZ * SLEN) /* 16384 */

// ---------------- device scratch (static, no allocations) ----------------
__device__ float d_E[(size_t)NROWS * HDIM];         // embeddings (tf32-rounded)
__device__ float d_CombIn[(size_t)NROWS * H2D];     // [hf | hb] per (t,b), rounded
__device__ float d_h[2][2][BSZ * HDIM];             // [dir][parity], rounded
__device__ float d_cfb[2][BSZ * HDIM];              // [dir], fp32
__device__ float d_hcb[2][BSZ * H2D];               // combiner h [parity], rounded
__device__ float d_cc[BSZ * H2D];                   // fp32
__device__ float d_hcfull[BSZ * H2D];               // final combiner h, FULL fp32 (head input)
__device__ float d_WihFr[4 * HDIM * HDIM];          // tf32-rounded weight copies
__device__ float d_WihBr[4 * HDIM * HDIM];
__device__ float d_WihCr[(size_t)4 * H2D * H2D];
__device__ float d_WhhFr[4 * HDIM * HDIM];
__device__ float d_WhhBr[4 * HDIM * HDIM];
__device__ float d_WhhCr[(size_t)4 * H2D * H2D];

// round-to-nearest-even into tf32 (10 explicit mantissa bits)
__device__ __forceinline__ float t32(float x) {
    unsigned u = __float_as_uint(x);
    unsigned r = (u + 0xFFFu + ((u >> 13) & 1u)) & 0xFFFFE000u;
    return __uint_as_float(r);
}
__device__ __forceinline__ float sigm(float x) { return 1.f / (1.f + __expf(-x)); }

__device__ __forceinline__ void cp16(void* dst, const void* src) {
    unsigned d = (unsigned)__cvta_generic_to_shared(dst);
    asm volatile("cp.async.cg.shared.global [%0], [%1], 16;" ::"r"(d), "l"(src));
}
__device__ __forceinline__ void cp_commit() { asm volatile("cp.async.commit_group;"); }
template <int N>
__device__ __forceinline__ void cp_wait() { asm volatile("cp.async.wait_group %0;" ::"n"(N)); }

// ---------------- fused prep: all weight roundings + state inits in ONE launch ------------
__global__ void __launch_bounds__(256) prep_kernel(
    const float* __restrict__ WihF, const float* __restrict__ WihB,
    const float* __restrict__ WhhF, const float* __restrict__ WhhB,
    const float* __restrict__ WihC, const float* __restrict__ WhhC,
    const float* __restrict__ h0f, const float* __restrict__ h0b, const float* __restrict__ h0c,
    const float* __restrict__ c0f, const float* __restrict__ c0b, const float* __restrict__ c0c) {
    int blk = blockIdx.x;
    const float* src;
    float* dst;
    int base;
    bool doround = true;
    if (blk < 1024)        { src = WihF; dst = d_WihFr; base = blk; }
    else if (blk < 2048)   { src = WihB; dst = d_WihBr; base = blk - 1024; }
    else if (blk < 3072)   { src = WhhF; dst = d_WhhFr; base = blk - 2048; }
    else if (blk < 4096)   { src = WhhB; dst = d_WhhBr; base = blk - 3072; }
    else if (blk < 8192)   { src = WihC; dst = d_WihCr; base = blk - 4096; }
    else if (blk < 12288)  { src = WhhC; dst = d_WhhCr; base = blk - 8192; }
    else if (blk < 12416)  { src = h0f; dst = d_h[0][0]; base = blk - 12288; }
    else if (blk < 12544)  { src = h0b; dst = d_h[1][0]; base = blk - 12416; }
    else if (blk < 12800)  { src = h0c; dst = d_hcb[0]; base = blk - 12544; }
    else if (blk < 12928)  { src = c0f; dst = d_cfb[0]; base = blk - 12800; doround = false; }
    else if (blk < 13056)  { src = c0b; dst = d_cfb[1]; base = blk - 12928; doround = false; }
    else                   { src = c0c; dst = d_cc;     base = blk - 13056; doround = false; }
    size_t i = (size_t)base * 256 + threadIdx.x;
    float4 v = ((const float4*)src)[i];
    if (doround) { v.x = t32(v.x); v.y = t32(v.y); v.z = t32(v.z); v.w = t32(v.w); }
    ((float4*)dst)[i] = v;
}

__global__ void embed_kernel(const int* __restrict__ x, const float* __restrict__ Wemb) {
    int r = blockIdx.x;
    int tok = x[r];
    float4* dst = (float4*)(d_E + (size_t)r * HDIM);
    if (tok == 0) {
        float4 z = {0.f, 0.f, 0.f, 0.f};
        dst[threadIdx.x] = z;
    } else {
        float4 v = ((const float4*)(Wemb + (size_t)tok * HDIM))[threadIdx.x];
        v.x = t32(v.x); v.y = t32(v.y); v.z = t32(v.z); v.w = t32(v.w);
        dst[threadIdx.x] = v;
    }
}

// ---------------- MERGED pair step: fb(t) on blocks [0,128), combiner(t-1) on [128,256) ----
// Both parts are fused-projection LSTM steps (no G buffers):
//   fb:   gates = [h | e_t] @ [Whh | Wih]^T,   K=1024 (16 chunks of 64)
//   comb: gates = [hc | x_t] @ [WhhC | WihC]^T, K=2048 (32 chunks of 64)
// c(t-1) reads CombIn(t-1), written by fb in the PREVIOUS launch -> launch-boundary ordered.
// smem per block: As[2][64][68] + Bs[2][128][68] = 104448 B -> 2 CTAs/SM, 256 blocks = 1 wave.
__global__ void __launch_bounds__(256) lstm_pair(
    const float* __restrict__ WhhF, const float* __restrict__ WhhB,
    const float* __restrict__ WihF, const float* __restrict__ WihB,
    const float* __restrict__ biF, const float* __restrict__ bhF,
    const float* __restrict__ biB, const float* __restrict__ bhB,
    const float* __restrict__ WhhC, const float* __restrict__ WihC,
    const float* __restrict__ biC, const float* __restrict__ bhC, int t) {
    extern __shared__ float sm[];
    float* As = sm;                  // [2][64][68]
    float* Bs = sm + 2 * 64 * 68;    // [2][128][68]
    float* gbuf = sm;                // overlay [64][132] after K loop

    const int tid = threadIdx.x;
    const int w = tid >> 5, wm = w >> 2, wn = w & 3;
    const int jje = tid & 31;

    if (blockIdx.x < 128) {
        // ================= fb part: step t =================
        if (t >= SLEN) return;
        const int bx = blockIdx.x;
        const int dir = bx >> 6;
        const int rem = bx & 63;
        const int m0 = (rem & 3) * 64;
        const int j0 = (rem >> 2) * 32;

        const float* Whh = dir ? WhhB : WhhF;
        const float* Wih = dir ? WihB : WihF;
        const float* bi = dir ? biB : biF;
        const float* bh = dir ? bhB : bhF;
        const float* hprev = d_h[dir][t & 1];
        float* hnext = d_h[dir][(t + 1) & 1];
        float* cst = d_cfb[dir];
        const int grow0 = (dir ? (SLEN - 1 - t) : t) * BSZ;
        const float* Et = d_E + (size_t)grow0 * HDIM;

        float bsum[4], cpre[8];
#pragma unroll
        for (int g = 0; g < 4; g++) bsum[g] = bi[g * HDIM + j0 + jje] + bh[g * HDIM + j0 + jje];
#pragma unroll
        for (int p = 0; p < 8; p++) {
            int b = m0 + (p * 256 + tid) / 32;
            cpre[p] = cst[(size_t)b * HDIM + j0 + jje];
        }

        wmma::fragment<wmma::accumulator, 16, 16, 8, float> cf[2][2];
#pragma unroll
        for (int i = 0; i < 2; i++)
#pragma unroll
            for (int j = 0; j < 2; j++) wmma::fill_fragment(cf[i][j], 0.f);

        {
#pragma unroll
            for (int i = 0; i < 4; i++) {
                int lin = tid + i * 256;
                int r = lin >> 4, c4 = (lin & 15) * 4;
                cp16(As + r * 68 + c4, hprev + (size_t)(m0 + r) * HDIM + c4);
            }
#pragma unroll
            for (int i = 0; i < 8; i++) {
                int lin = tid + i * 256;
                int rr = lin >> 4, cc = (lin & 15) * 4;
                int gr = (rr >> 5) * HDIM + j0 + (rr & 31);
                cp16(Bs + rr * 68 + cc, Whh + (size_t)gr * HDIM + cc);
            }
            cp_commit();
        }
        int buf = 0;
#pragma unroll 1
        for (int kt = 0; kt < 16; kt++) {
            cp_wait<0>();
            __syncthreads();
            if (kt < 15) {
                int nkt = kt + 1;
                const float* Ab = (nkt < 8) ? hprev : Et;
                const float* Bb = (nkt < 8) ? Whh : Wih;
                int ko = (nkt & 7) * 64;
                int nb = buf ^ 1;
#pragma unroll
                for (int i = 0; i < 4; i++) {
                    int lin = tid + i * 256;
                    int r = lin >> 4, c4 = (lin & 15) * 4;
                    cp16(As + nb * 4352 + r * 68 + c4, Ab + (size_t)(m0 + r) * HDIM + ko + c4);
                }
#pragma unroll
                for (int i = 0; i < 8; i++) {
                    int lin = tid + i * 256;
                    int rr = lin >> 4, cc = (lin & 15) * 4;
                    int gr = (rr >> 5) * HDIM + j0 + (rr & 31);
                    cp16(Bs + nb * 8704 + rr * 68 + cc, Bb + (size_t)gr * HDIM + ko + cc);
                }
                cp_commit();
            }
#pragma unroll
            for (int ks = 0; ks < 8; ks++) {
                wmma::fragment<wmma::matrix_a, 16, 16, 8, wmma::precision::tf32, wmma::row_major> af[2];
                wmma::fragment<wmma::matrix_b, 16, 16, 8, wmma::precision::tf32, wmma::col_major> bf[2];
#pragma unroll
                for (int i = 0; i < 2; i++)
                    wmma::load_matrix_sync(af[i], As + buf * 4352 + (wm * 32 + i * 16) * 68 + ks * 8, 68);
#pragma unroll
                for (int j = 0; j < 2; j++)
                    wmma::load_matrix_sync(bf[j], Bs + buf * 8704 + (wn * 32 + j * 16) * 68 + ks * 8, 68);
#pragma unroll
                for (int i = 0; i < 2; i++)
#pragma unroll
                    for (int j = 0; j < 2; j++) wmma::mma_sync(cf[i][j], af[i], bf[j], cf[i][j]);
            }
            buf ^= 1;
        }
        __syncthreads();
#pragma unroll
        for (int i = 0; i < 2; i++)
#pragma unroll
            for (int j = 0; j < 2; j++)
                wmma::store_matrix_sync(gbuf + (wm * 32 + i * 16) * 132 + wn * 32 + j * 16, cf[i][j],
                                        132, wmma::mem_row_major);
        __syncthreads();

#pragma unroll
        for (int p = 0; p < 8; p++) {
            int idx = p * 256 + tid;
            int m = idx >> 5, jj = idx & 31;
            int b = m0 + m, j = j0 + jj;
            float ip = gbuf[m * 132 + jj]      + bsum[0];
            float fp = gbuf[m * 132 + 32 + jj] + bsum[1];
            float gp = gbuf[m * 132 + 64 + jj] + bsum[2];
            float op = gbuf[m * 132 + 96 + jj] + bsum[3];
            float cn = sigm(fp) * cpre[p] + sigm(ip) * tanhf(gp);
            cst[(size_t)b * HDIM + j] = cn;
            float hr = t32(sigm(op) * tanhf(cn));
            hnext[(size_t)b * HDIM + j] = hr;
            d_CombIn[(size_t)(t * BSZ + b) * H2D + dir * HDIM + j] = hr;
        }
    } else {
        // ================= combiner part: step t-1 =================
        const int tc = t - 1;
        if (tc < 0) return;
        const int bx = blockIdx.x - 128;
        const int m0 = (bx & 3) * 64;
        const int j0 = (bx >> 2) * 32;

        const float* hprev = d_hcb[tc & 1];
        float* hnext = d_hcb[(tc + 1) & 1];
        const float* Xt = d_CombIn + (size_t)tc * BSZ * H2D;

        float bsum[4], cpre[8];
#pragma unroll
        for (int g = 0; g < 4; g++) bsum[g] = biC[g * H2D + j0 + jje] + bhC[g * H2D + j0 + jje];
#pragma unroll
        for (int p = 0; p < 8; p++) {
            int b = m0 + (p * 256 + tid) / 32;
            cpre[p] = d_cc[(size_t)b * H2D + j0 + jje];
        }

        wmma::fragment<wmma::accumulator, 16, 16, 8, float> cf[2][2];
#pragma unroll
        for (int i = 0; i < 2; i++)
#pragma unroll
            for (int j = 0; j < 2; j++) wmma::fill_fragment(cf[i][j], 0.f);

        {
#pragma unroll
            for (int i = 0; i < 4; i++) {
                int lin = tid + i * 256;
                int r = lin >> 4, c4 = (lin & 15) * 4;
                cp16(As + r * 68 + c4, hprev + (size_t)(m0 + r) * H2D + c4);
            }
#pragma unroll
            for (int i = 0; i < 8; i++) {
                int lin = tid + i * 256;
                int rr = lin >> 4, cc = (lin & 15) * 4;
                int gr = (rr >> 5) * H2D + j0 + (rr & 31);
                cp16(Bs + rr * 68 + cc, WhhC + (size_t)gr * H2D + cc);
            }
            cp_commit();
        }
        int buf = 0;
#pragma unroll 1
        for (int kt = 0; kt < 32; kt++) {
            cp_wait<0>();
            __syncthreads();
            if (kt < 31) {
                int nkt = kt + 1;
                const float* Ab = (nkt < 16) ? hprev : Xt;
                const float* Bb = (nkt < 16) ? WhhC : WihC;
                int ko = (nkt & 15) * 64;
                int nb = buf ^ 1;
#pragma unroll
                for (int i = 0; i < 4; i++) {
                    int lin = tid + i * 256;
                    int r = lin >> 4, c4 = (lin & 15) * 4;
                    cp16(As + nb * 4352 + r * 68 + c4, Ab + (size_t)(m0 + r) * H2D + ko + c4);
                }
#pragma unroll
                for (int i = 0; i < 8; i++) {
                    int lin = tid + i * 256;
                    int rr = lin >> 4, cc = (lin & 15) * 4;
                    int gr = (rr >> 5) * H2D + j0 + (rr & 31);
                    cp16(Bs + nb * 8704 + rr * 68 + cc, Bb + (size_t)gr * H2D + ko + cc);
                }
                cp_commit();
            }
#pragma unroll
            for (int ks = 0; ks < 8; ks++) {
                wmma::fragment<wmma::matrix_a, 16, 16, 8, wmma::precision::tf32, wmma::row_major> af[2];
                wmma::fragment<wmma::matrix_b, 16, 16, 8, wmma::precision::tf32, wmma::col_major> bf[2];
#pragma unroll
                for (int i = 0; i < 2; i++)
                    wmma::load_matrix_sync(af[i], As + buf * 4352 + (wm * 32 + i * 16) * 68 + ks * 8, 68);
#pragma unroll
                for (int j = 0; j < 2; j++)
                    wmma::load_matrix_sync(bf[j], Bs + buf * 8704 + (wn * 32 + j * 16) * 68 + ks * 8, 68);
#pragma unroll
                for (int i = 0; i < 2; i++)
#pragma unroll
                    for (int j = 0; j < 2; j++) wmma::mma_sync(cf[i][j], af[i], bf[j], cf[i][j]);
            }
            buf ^= 1;
        }
        __syncthreads();
#pragma unroll
        for (int i = 0; i < 2; i++)
#pragma unroll
            for (int j = 0; j < 2; j++)
                wmma::store_matrix_sync(gbuf + (wm * 32 + i * 16) * 132 + wn * 32 + j * 16, cf[i][j],
                                        132, wmma::mem_row_major);
        __syncthreads();

#pragma unroll
        for (int p = 0; p < 8; p++) {
            int idx = p * 256 + tid;
            int m = idx >> 5, jj = idx & 31;
            int b = m0 + m, j = j0 + jj;
            float ip = gbuf[m * 132 + jj]      + bsum[0];
            float fp = gbuf[m * 132 + 32 + jj] + bsum[1];
            float gp = gbuf[m * 132 + 64 + jj] + bsum[2];
            float op = gbuf[m * 132 + 96 + jj] + bsum[3];
            float cn = sigm(fp) * cpre[p] + sigm(ip) * tanhf(gp);
            d_cc[(size_t)b * H2D + j] = cn;
            float hn = sigm(op) * tanhf(cn);
            hnext[(size_t)b * H2D + j] = t32(hn);
            if (tc == SLEN - 1) d_hcfull[(size_t)b * H2D + j] = hn;
        }
    }
}

// ---------------- head: 3xTF32 error-compensated GEMM (fp32-accurate) ----------------
__global__ void __launch_bounds__(256) head3_kernel(const float* __restrict__ A,
                                                    const float* __restrict__ W,
                                                    float* __restrict__ C) {
    extern __shared__ float sm[];
    float(*Ahi)[36] = (float(*)[36])sm;
    float(*Alo)[36] = (float(*)[36])(sm + 128 * 36);
    float(*Bhi)[36] = (float(*)[36])(sm + 2 * 128 * 36);
    float(*Blo)[36] = (float(*)[36])(sm + 3 * 128 * 36);
    const int K = H2D, N = VDIM;
    const int m0 = blockIdx.y * 128, n0 = blockIdx.x * 128;
    const int tid = threadIdx.x;
    const int w = tid >> 5, wm = w >> 1, wn = w & 1;

    wmma::fragment<wmma::accumulator, 16, 16, 8, float> cf[2][4];
#pragma unroll
    for (int i = 0; i < 2; i++)
#pragma unroll
        for (int j = 0; j < 4; j++) wmma::fill_fragment(cf[i][j], 0.f);

    for (int k0 = 0; k0 < K; k0 += 32) {
#pragma unroll
        for (int i = 0; i < 4; i++) {
            int lin = tid + i * 256;
            int r = lin >> 3, c4 = (lin & 7) * 4;
            float4 v = *(const float4*)(A + (size_t)(m0 + r) * K + k0 + c4);
            float4 hi, lo;
            hi.x = t32(v.x); lo.x = t32(v.x - hi.x);
            hi.y = t32(v.y); lo.y = t32(v.y - hi.y);
            hi.z = t32(v.z); lo.z = t32(v.z - hi.z);
            hi.w = t32(v.w); lo.w = t32(v.w - hi.w);
            *(float4*)(&Ahi[r][c4]) = hi;
            *(float4*)(&Alo[r][c4]) = lo;
        }
#pragma unroll
        for (int i = 0; i < 4; i++) {
            int lin = tid + i * 256;
            int r = lin >> 3, c4 = (lin & 7) * 4;
            float4 v = *(const float4*)(W + (size_t)(n0 + r) * K + k0 + c4);
            float4 hi, lo;
            hi.x = t32(v.x); lo.x = t32(v.x - hi.x);
            hi.y = t32(v.y); lo.y = t32(v.y - hi.y);
            hi.z = t32(v.z); lo.z = t32(v.z - hi.z);
            hi.w = t32(v.w); lo.w = t32(v.w - hi.w);
            *(float4*)(&Bhi[r][c4]) = hi;
            *(float4*)(&Blo[r][c4]) = lo;
        }
        __syncthreads();
#pragma unroll
        for (int ks = 0; ks < 4; ks++) {
            wmma::fragment<wmma::matrix_a, 16, 16, 8, wmma::precision::tf32, wmma::row_major> ah[2], al[2];
            wmma::fragment<wmma::matrix_b, 16, 16, 8, wmma::precision::tf32, wmma::col_major> bhf[4], blf[4];
#pragma unroll
            for (int i = 0; i < 2; i++) {
                wmma::load_matrix_sync(ah[i], &Ahi[wm * 32 + i * 16][ks * 8], 36);
                wmma::load_matrix_sync(al[i], &Alo[wm * 32 + i * 16][ks * 8], 36);
            }
#pragma unroll
            for (int j = 0; j < 4; j++) {
                wmma::load_matrix_sync(bhf[j], &Bhi[wn * 64 + j * 16][ks * 8], 36);
                wmma::load_matrix_sync(blf[j], &Blo[wn * 64 + j * 16][ks * 8], 36);
            }
#pragma unroll
            for (int i = 0; i < 2; i++)
#pragma unroll
                for (int j = 0; j < 4; j++) {
                    wmma::mma_sync(cf[i][j], al[i], bhf[j], cf[i][j]);
                    wmma::mma_sync(cf[i][j], ah[i], blf[j], cf[i][j]);
                    wmma::mma_sync(cf[i][j], ah[i], bhf[j], cf[i][j]);
                }
        }
        __syncthreads();
    }
#pragma unroll
    for (int i = 0; i < 2; i++)
#pragma unroll
        for (int j = 0; j < 4; j++)
            wmma::store_matrix_sync(C + (size_t)(m0 + wm * 32 + i * 16) * N + n0 + wn * 64 + j * 16,
                                    cf[i][j], N, wmma::mem_row_major);
}

__global__ void bias_add_kernel(float* __restrict__ C, const float* __restrict__ bout) {
    size_t idx = (size_t)blockIdx.x * 256 + threadIdx.x;
    float4 v = ((float4*)C)[idx];
    int n = (int)(idx % (VDIM / 4)) * 4;
    v.x += bout[n]; v.y += bout[n + 1]; v.z += bout[n + 2]; v.w += bout[n + 3];
    ((float4*)C)[idx] = v;
}

// ---------------- host orchestration (single stream) ----------------
extern "C" void kernel_launch(void* const* d_in, const int* in_sizes, int n_in,
                              void* d_out, int out_size) {
    (void)in_sizes; (void)n_in; (void)out_size;
    const int* x = (const int*)d_in[0];
    const float* Wemb = (const float*)d_in[1];
    const float* WihF = (const float*)d_in[2];
    const float* WhhF = (const float*)d_in[3];
    const float* biF = (const float*)d_in[4];
    const float* bhF = (const float*)d_in[5];
    const float* WihB = (const float*)d_in[6];
    const float* WhhB = (const float*)d_in[7];
    const float* biB = (const float*)d_in[8];
    const float* bhB = (const float*)d_in[9];
    const float* WihC = (const float*)d_in[10];
    const float* WhhC = (const float*)d_in[11];
    const float* biC = (const float*)d_in[12];
    const float* bhC = (const float*)d_in[13];
    const float* Wout = (const float*)d_in[14];
    const float* bout = (const float*)d_in[15];
    const float* h0f = (const float*)d_in[16];
    const float* c0f = (const float*)d_in[17];
    const float* h0b = (const float*)d_in[18];
    const float* c0b = (const float*)d_in[19];
    const float* h0c = (const float*)d_in[20];
    const float* c0c = (const float*)d_in[21];
    float* out = (float*)d_out;

    void *phcf, *pWiF, *pWiB, *pWiC, *pWhF, *pWhB, *pWhC;
    cudaGetSymbolAddress(&phcf, d_hcfull);
    cudaGetSymbolAddress(&pWiF, d_WihFr);
    cudaGetSymbolAddress(&pWiB, d_WihBr);
    cudaGetSymbolAddress(&pWiC, d_WihCr);
    cudaGetSymbolAddress(&pWhF, d_WhhFr);
    cudaGetSymbolAddress(&pWhB, d_WhhBr);
    cudaGetSymbolAddress(&pWhC, d_WhhCr);

    cudaFuncSetAttribute(head3_kernel, cudaFuncAttributeMaxDynamicSharedMemorySize, 73728);
    cudaFuncSetAttribute(lstm_pair, cudaFuncAttributeMaxDynamicSharedMemorySize, 104448);

    // launch 0: fused prep; launch 1: embedding
    prep_kernel<<<13312, 256>>>(WihF, WihB, WhhF, WhhB, WihC, WhhC,
                                h0f, h0b, h0c, c0f, c0b, c0c);
    embed_kernel<<<NROWS, 128>>>(x, Wemb);

    // merged recurrence: launch t runs fb(t) and combiner(t-1) concurrently (65 launches)
    for (int t = 0; t <= SLEN; t++)
        lstm_pair<<<256, 256, 104448>>>(
            (const float*)pWhF, (const float*)pWhB, (const float*)pWiF, (const float*)pWiB,
            biF, bhF, biB, bhB,
            (const float*)pWhC, (const float*)pWiC, biC, bhC, t);

    // output head (3xTF32) + bias
    head3_kernel<<<dim3(VDIM / 128, BSZ / 128), 256, 73728>>>((const float*)phcf, Wout, out);
    bias_add_kernel<<<(BSZ * VDIM / 4) / 256, 256>>>(out, bout);
}

// round 12
// speedup vs baseline: 1.3603x; 1.3603x over previous
#include <cuda_runtime.h>
#include <mma.h>

using namespace nvcuda;

#define BSZ 256
#define SLEN 64
#define HDIM 512
#define H2D 1024
#define VDIM 32000
#define NROWS (BSZ * SLEN) /* 16384 */

// ---------------- device scratch (static, no allocations) ----------------
__device__ float d_E[(size_t)NROWS * HDIM];         // embeddings (tf32-rounded)
__device__ float d_Gf[(size_t)NROWS * 4 * HDIM];    // fwd input preacts [sample][2048]
__device__ float d_Gb[(size_t)NROWS * 4 * HDIM];    // bwd input preacts
__device__ float d_CombIn[(size_t)NROWS * H2D];     // [hf | hb] per (t,b), rounded
__device__ float d_Gc[(size_t)NROWS * 4 * H2D];     // combiner input preacts [sample][4096]
__device__ float d_h[2][2][BSZ * HDIM];             // [dir][parity], rounded
__device__ float d_cfb[2][BSZ * HDIM];              // [dir], fp32
__device__ float d_hcb[2][BSZ * H2D];               // combiner h [parity], rounded
__device__ float d_cc[BSZ * H2D];                   // fp32
__device__ float d_hcfull[BSZ * H2D];               // final combiner h, FULL fp32 (head input)
__device__ float d_WihFr[4 * HDIM * HDIM];          // tf32-rounded weight copies
__device__ float d_WihBr[4 * HDIM * HDIM];
__device__ float d_WihCr[(size_t)4 * H2D * H2D];
__device__ float d_WhhFr[4 * HDIM * HDIM];
__device__ float d_WhhBr[4 * HDIM * HDIM];
__device__ float d_WhhCr[(size_t)4 * H2D * H2D];

// round-to-nearest-even into tf32 (10 explicit mantissa bits)
__device__ __forceinline__ float t32(float x) {
    unsigned u = __float_as_uint(x);
    unsigned r = (u + 0xFFFu + ((u >> 13) & 1u)) & 0xFFFFE000u;
    return __uint_as_float(r);
}
__device__ __forceinline__ float sigm(float x) { return 1.f / (1.f + __expf(-x)); }

__device__ __forceinline__ void cp16(void* dst, const void* src) {
    unsigned d = (unsigned)__cvta_generic_to_shared(dst);
    asm volatile("cp.async.cg.shared.global [%0], [%1], 16;" ::"r"(d), "l"(src));
}
__device__ __forceinline__ void cp_commit() { asm volatile("cp.async.commit_group;"); }
template <int N>
__device__ __forceinline__ void cp_wait() { asm volatile("cp.async.wait_group %0;" ::"n"(N)); }

// ---- mbarrier + bulk-copy helpers (sm_90+; valid on sm_103a) ----
__device__ __forceinline__ void mbar_init(unsigned bar, unsigned cnt) {
    asm volatile("mbarrier.init.shared.b64 [%0], %1;" ::"r"(bar), "r"(cnt) : "memory");
}
__device__ __forceinline__ void mbar_expect_tx(unsigned bar, unsigned bytes) {
    asm volatile("mbarrier.arrive.expect_tx.shared.b64 _, [%0], %1;" ::"r"(bar), "r"(bytes)
                 : "memory");
}
__device__ __forceinline__ void bulk_cp(unsigned dst, const void* src, unsigned bytes,
                                        unsigned bar) {
    asm volatile(
        "cp.async.bulk.shared::cta.global.mbarrier::complete_tx::bytes [%0], [%1], %2, [%3];"
        ::"r"(dst), "l"(src), "r"(bytes), "r"(bar)
        : "memory");
}
__device__ __forceinline__ void mbar_wait(unsigned bar, unsigned parity) {
    asm volatile(
        "{\n\t"
        ".reg .pred P1;\n\t"
        "WAIT_LOOP_%=:\n\t"
        "mbarrier.try_wait.parity.acquire.cta.shared::cta.b64 P1, [%0], %1, 0x989680;\n\t"
        "@P1 bra.uni WAIT_DONE_%=;\n\t"
        "bra.uni WAIT_LOOP_%=;\n\t"
        "WAIT_DONE_%=:\n\t"
        "}"
        ::"r"(bar), "r"(parity)
        : "memory");
}

// ---------------- fused prep: all weight roundings + state inits in ONE launch ------------
__global__ void __launch_bounds__(256) prep_kernel(
    const float* __restrict__ WihF, const float* __restrict__ WihB,
    const float* __restrict__ WhhF, const float* __restrict__ WhhB,
    const float* __restrict__ WihC, const float* __restrict__ WhhC,
    const float* __restrict__ h0f, const float* __restrict__ h0b, const float* __restrict__ h0c,
    const float* __restrict__ c0f, const float* __restrict__ c0b, const float* __restrict__ c0c) {
    int blk = blockIdx.x;
    const float* src;
    float* dst;
    int base;
    bool doround = true;
    if (blk < 1024)        { src = WihF; dst = d_WihFr; base = blk; }
    else if (blk < 2048)   { src = WihB; dst = d_WihBr; base = blk - 1024; }
    else if (blk < 3072)   { src = WhhF; dst = d_WhhFr; base = blk - 2048; }
    else if (blk < 4096)   { src = WhhB; dst = d_WhhBr; base = blk - 3072; }
    else if (blk < 8192)   { src = WihC; dst = d_WihCr; base = blk - 4096; }
    else if (blk < 12288)  { src = WhhC; dst = d_WhhCr; base = blk - 8192; }
    else if (blk < 12416)  { src = h0f; dst = d_h[0][0]; base = blk - 12288; }
    else if (blk < 12544)  { src = h0b; dst = d_h[1][0]; base = blk - 12416; }
    else if (blk < 12800)  { src = h0c; dst = d_hcb[0]; base = blk - 12544; }
    else if (blk < 12928)  { src = c0f; dst = d_cfb[0]; base = blk - 12800; doround = false; }
    else if (blk < 13056)  { src = c0b; dst = d_cfb[1]; base = blk - 12928; doround = false; }
    else                   { src = c0c; dst = d_cc;     base = blk - 13056; doround = false; }
    size_t i = (size_t)base * 256 + threadIdx.x;
    float4 v = ((const float4*)src)[i];
    if (doround) { v.x = t32(v.x); v.y = t32(v.y); v.z = t32(v.z); v.w = t32(v.w); }
    ((float4*)dst)[i] = v;
}

__global__ void embed_kernel(const int* __restrict__ x, const float* __restrict__ Wemb) {
    int r = blockIdx.x;
    int tok = x[r];
    float4* dst = (float4*)(d_E + (size_t)r * HDIM);
    if (tok == 0) {
        float4 z = {0.f, 0.f, 0.f, 0.f};
        dst[threadIdx.x] = z;
    } else {
        float4 v = ((const float4*)(Wemb + (size_t)tok * HDIM))[threadIdx.x];
        v.x = t32(v.x); v.y = t32(v.y); v.z = t32(v.z); v.w = t32(v.w);
        dst[threadIdx.x] = v;
    }
}

// ---------------- TF32 GEMM on PRE-ROUNDED operands, cp.async double-buffered ----------
// C[M,N] = A[M,K] @ W[N,K]^T. block tile 128x128, BK=32, 256 threads (8 warps 4x2).
__global__ void __launch_bounds__(256, 2) gemm_pre(const float* __restrict__ A,
                                                   const float* __restrict__ W,
                                                   float* __restrict__ C,
                                                   int M, int N, int K) {
    extern __shared__ float sm[];
    float* As = sm;                 // [2][128][36]
    float* Bs = sm + 2 * 128 * 36;  // [2][128][36]
    const int m0 = blockIdx.y * 128, n0 = blockIdx.x * 128;
    const int tid = threadIdx.x;
    const int w = tid >> 5, wm = w >> 1, wn = w & 1;
    const int KT = K >> 5;

    wmma::fragment<wmma::accumulator, 16, 16, 8, float> cf[2][4];
#pragma unroll
    for (int i = 0; i < 2; i++)
#pragma unroll
        for (int j = 0; j < 4; j++) wmma::fill_fragment(cf[i][j], 0.f);

    {
#pragma unroll
        for (int i = 0; i < 4; i++) {
            int lin = tid + i * 256;
            int r = lin >> 3, c4 = (lin & 7) * 4;
            cp16(As + r * 36 + c4, A + (size_t)(m0 + r) * K + c4);
            cp16(Bs + r * 36 + c4, W + (size_t)(n0 + r) * K + c4);
        }
        cp_commit();
    }
    int buf = 0;
#pragma unroll 1
    for (int kt = 0; kt < KT; kt++) {
        cp_wait<0>();
        __syncthreads();
        if (kt + 1 < KT) {
            int nb = buf ^ 1;
#pragma unroll
            for (int i = 0; i < 4; i++) {
                int lin = tid + i * 256;
                int r = lin >> 3, c4 = (lin & 7) * 4;
                cp16(As + nb * 4608 + r * 36 + c4, A + (size_t)(m0 + r) * K + (kt + 1) * 32 + c4);
                cp16(Bs + nb * 4608 + r * 36 + c4, W + (size_t)(n0 + r) * K + (kt + 1) * 32 + c4);
            }
            cp_commit();
        }
#pragma unroll
        for (int ks = 0; ks < 4; ks++) {
            wmma::fragment<wmma::matrix_a, 16, 16, 8, wmma::precision::tf32, wmma::row_major> af[2];
            wmma::fragment<wmma::matrix_b, 16, 16, 8, wmma::precision::tf32, wmma::col_major> bf[4];
#pragma unroll
            for (int i = 0; i < 2; i++)
                wmma::load_matrix_sync(af[i], As + buf * 4608 + (wm * 32 + i * 16) * 36 + ks * 8, 36);
#pragma unroll
            for (int j = 0; j < 4; j++)
                wmma::load_matrix_sync(bf[j], Bs + buf * 4608 + (wn * 64 + j * 16) * 36 + ks * 8, 36);
#pragma unroll
            for (int i = 0; i < 2; i++)
#pragma unroll
                for (int j = 0; j < 4; j++) wmma::mma_sync(cf[i][j], af[i], bf[j], cf[i][j]);
        }
        buf ^= 1;
    }
#pragma unroll
    for (int i = 0; i < 2; i++)
#pragma unroll
        for (int j = 0; j < 4; j++)
            wmma::store_matrix_sync(C + (size_t)(m0 + wm * 32 + i * 16) * N + n0 + wn * 64 + j * 16,
                                    cf[i][j], N, wmma::mem_row_major);
}

// ---------------- LSTM step fwd+bwd: BULK-COPY pipeline, BK=128, M=64 tile ----------------
// grid (4, 16, 2) = 128 blocks (1 wave). 256 threads, warps 2(m) x 4(n), cf[2][2].
// smem: As[2][64][132] + Bs[2][128][132] + 2 mbarriers = 202768 B  (1 CTA/SM)
// Producers: threads 0..127 -> B rows (512B bulk each), threads 128..191 -> A rows.
#define STEP_SMEM (2 * 64 * 132 * 4 + 2 * 128 * 132 * 4 + 16)
__global__ void __launch_bounds__(256) lstm_step_fb(
    const float* __restrict__ WhhF, const float* __restrict__ WhhB,
    const float* __restrict__ biF, const float* __restrict__ bhF,
    const float* __restrict__ biB, const float* __restrict__ bhB, int t) {
    extern __shared__ float sm[];
    float* As = sm;                    // [2][64][132]
    float* Bs = sm + 2 * 64 * 132;     // [2][128][132]
    float* gbuf = sm;                  // overlay [64][132] (== As stage 0)
    const unsigned smb = (unsigned)__cvta_generic_to_shared(sm);
    const unsigned barb = smb + (2 * 64 * 132 + 2 * 128 * 132) * 4;

    const int dir = blockIdx.z;
    const float* Whh = dir ? WhhB : WhhF;
    const float* bi = dir ? biB : biF;
    const float* bh = dir ? bhB : bhF;
    const float* hprev = d_h[dir][t & 1];
    float* hnext = d_h[dir][(t + 1) & 1];
    float* cst = d_cfb[dir];
    const float* G = dir ? d_Gb : d_Gf;
    const int grow0 = (dir ? (SLEN - 1 - t) : t) * BSZ;

    const int m0 = blockIdx.x * 64;
    const int j0 = blockIdx.y * 32;
    const int tid = threadIdx.x;
    const int w = tid >> 5, wm = w >> 2, wn = w & 3;

    // hoisted epilogue operand loads (overlap with pipeline below)
    float gpre[8][4], cpre[8], bsum[8][4];
#pragma unroll
    for (int p = 0; p < 8; p++) {
        int idx = p * 256 + tid;
        int m = idx >> 5, jj = idx & 31;
        int b = m0 + m, j = j0 + jj;
        const float* grow = G + (size_t)(grow0 + b) * (4 * HDIM);
        gpre[p][0] = grow[j];
        gpre[p][1] = grow[HDIM + j];
        gpre[p][2] = grow[2 * HDIM + j];
        gpre[p][3] = grow[3 * HDIM + j];
        cpre[p] = cst[(size_t)b * HDIM + j];
        bsum[p][0] = bi[j] + bh[j];
        bsum[p][1] = bi[HDIM + j] + bh[HDIM + j];
        bsum[p][2] = bi[2 * HDIM + j] + bh[2 * HDIM + j];
        bsum[p][3] = bi[3 * HDIM + j] + bh[3 * HDIM + j];
    }

    if (tid == 0) {
        mbar_init(barb, 192);
        mbar_init(barb + 8, 192);
    }
    __syncthreads();

    // producer row sources (fixed per thread)
    const float* srcRow = nullptr;
    unsigned dstBase = 0;
    if (tid < 128) {  // B row
        int gr = (tid >> 5) * HDIM + j0 + (tid & 31);
        srcRow = Whh + (size_t)gr * HDIM;
        dstBase = smb + (2 * 64 * 132 + tid * 132) * 4;   // Bs stage 0 row tid
    } else if (tid < 192) {  // A row
        int r = tid - 128;
        srcRow = hprev + (size_t)(m0 + r) * HDIM;
        dstBase = smb + (r * 132) * 4;                    // As stage 0 row r
    }
    const unsigned stageOffB = 128 * 132 * 4;  // Bs stage stride (bytes)
    const unsigned stageOffA = 64 * 132 * 4;   // As stage stride (bytes)
    const unsigned myStageOff = (tid < 128) ? stageOffB : stageOffA;

    wmma::fragment<wmma::accumulator, 16, 16, 8, float> cf[2][2];
#pragma unroll
    for (int i = 0; i < 2; i++)
#pragma unroll
        for (int j = 0; j < 2; j++) wmma::fill_fragment(cf[i][j], 0.f);

    // prologue: chunk 0 -> stage 0
    if (tid < 192) {
        mbar_expect_tx(barb, 512);
        bulk_cp(dstBase, srcRow, 512, barb);
    }
#pragma unroll 1
    for (int kt = 0; kt < 4; kt++) {  // K = 512, BK = 128
        int st = kt & 1;
        mbar_wait(barb + 8 * st, (kt >> 1) & 1);
        __syncthreads();
        if (kt < 3 && tid < 192) {
            int ns = (kt + 1) & 1;
            unsigned nbar = barb + 8 * ns;
            mbar_expect_tx(nbar, 512);
            bulk_cp(dstBase + ns * myStageOff, srcRow + (kt + 1) * 128, 512, nbar);
        }
#pragma unroll
        for (int ks = 0; ks < 16; ks++) {
            wmma::fragment<wmma::matrix_a, 16, 16, 8, wmma::precision::tf32, wmma::row_major> af[2];
            wmma::fragment<wmma::matrix_b, 16, 16, 8, wmma::precision::tf32, wmma::col_major> bf[2];
#pragma unroll
            for (int i = 0; i < 2; i++)
                wmma::load_matrix_sync(af[i], As + st * 64 * 132 + (wm * 32 + i * 16) * 132 + ks * 8,
                                       132);
#pragma unroll
            for (int j = 0; j < 2; j++)
                wmma::load_matrix_sync(bf[j],
                                       Bs + st * 128 * 132 + (wn * 32 + j * 16) * 132 + ks * 8, 132);
#pragma unroll
            for (int i = 0; i < 2; i++)
#pragma unroll
                for (int j = 0; j < 2; j++) wmma::mma_sync(cf[i][j], af[i], bf[j], cf[i][j]);
        }
    }
    __syncthreads();
#pragma unroll
    for (int i = 0; i < 2; i++)
#pragma unroll
        for (int j = 0; j < 2; j++)
            wmma::store_matrix_sync(gbuf + (wm * 32 + i * 16) * 132 + wn * 32 + j * 16, cf[i][j],
                                    132, wmma::mem_row_major);
    __syncthreads();

#pragma unroll
    for (int p = 0; p < 8; p++) {  // 64x32 cell elements
        int idx = p * 256 + tid;
        int m = idx >> 5, jj = idx & 31;
        int b = m0 + m, j = j0 + jj;
        float ip = gbuf[m * 132 + jj]      + gpre[p][0] + bsum[p][0];
        float fp = gbuf[m * 132 + 32 + jj] + gpre[p][1] + bsum[p][1];
        float gp = gbuf[m * 132 + 64 + jj] + gpre[p][2] + bsum[p][2];
        float op = gbuf[m * 132 + 96 + jj] + gpre[p][3] + bsum[p][3];
        float cn = sigm(fp) * cpre[p] + sigm(ip) * tanhf(gp);
        cst[(size_t)b * HDIM + j] = cn;
        float hr = t32(sigm(op) * tanhf(cn));
        hnext[(size_t)b * HDIM + j] = hr;
        d_CombIn[(size_t)(t * BSZ + b) * H2D + dir * HDIM + j] = hr;
    }
}

// ---------------- combiner LSTM step (H=1024): BULK-COPY pipeline, BK=128, M=64 ----------
// grid (4, 32) = 128 blocks (1 wave).
__global__ void __launch_bounds__(256) lstm_step_c(
    const float* __restrict__ Whh, const float* __restrict__ bi,
    const float* __restrict__ bh, int t) {
    extern __shared__ float sm[];
    float* As = sm;
    float* Bs = sm + 2 * 64 * 132;
    float* gbuf = sm;
    const unsigned smb = (unsigned)__cvta_generic_to_shared(sm);
    const unsigned barb = smb + (2 * 64 * 132 + 2 * 128 * 132) * 4;

    const float* hprev = d_hcb[t & 1];
    float* hnext = d_hcb[(t + 1) & 1];
    const int grow0 = t * BSZ;

    const int m0 = blockIdx.x * 64;
    const int j0 = blockIdx.y * 32;
    const int tid = threadIdx.x;
    const int w = tid >> 5, wm = w >> 2, wn = w & 3;

    float gpre[8][4], cpre[8], bsum[8][4];
#pragma unroll
    for (int p = 0; p < 8; p++) {
        int idx = p * 256 + tid;
        int m = idx >> 5, jj = idx & 31;
        int b = m0 + m, j = j0 + jj;
        const float* grow = d_Gc + (size_t)(grow0 + b) * (4 * H2D);
        gpre[p][0] = grow[j];
        gpre[p][1] = grow[H2D + j];
        gpre[p][2] = grow[2 * H2D + j];
        gpre[p][3] = grow[3 * H2D + j];
        cpre[p] = d_cc[(size_t)b * H2D + j];
        bsum[p][0] = bi[j] + bh[j];
        bsum[p][1] = bi[H2D + j] + bh[H2D + j];
        bsum[p][2] = bi[2 * H2D + j] + bh[2 * H2D + j];
        bsum[p][3] = bi[3 * H2D + j] + bh[3 * H2D + j];
    }

    if (tid == 0) {
        mbar_init(barb, 192);
        mbar_init(barb + 8, 192);
    }
    __syncthreads();

    const float* srcRow = nullptr;
    unsigned dstBase = 0;
    if (tid < 128) {
        int gr = (tid >> 5) * H2D + j0 + (tid & 31);
        srcRow = Whh + (size_t)gr * H2D;
        dstBase = smb + (2 * 64 * 132 + tid * 132) * 4;
    } else if (tid < 192) {
        int r = tid - 128;
        srcRow = hprev + (size_t)(m0 + r) * H2D;
        dstBase = smb + (r * 132) * 4;
    }
    const unsigned stageOffB = 128 * 132 * 4;
    const unsigned stageOffA = 64 * 132 * 4;
    const unsigned myStageOff = (tid < 128) ? stageOffB : stageOffA;

    wmma::fragment<wmma::accumulator, 16, 16, 8, float> cf[2][2];
#pragma unroll
    for (int i = 0; i < 2; i++)
#pragma unroll
        for (int j = 0; j < 2; j++) wmma::fill_fragment(cf[i][j], 0.f);

    if (tid < 192) {
        mbar_expect_tx(barb, 512);
        bulk_cp(dstBase, srcRow, 512, barb);
    }
#pragma unroll 1
    for (int kt = 0; kt < 8; kt++) {  // K = 1024, BK = 128
        int st = kt & 1;
        mbar_wait(barb + 8 * st, (kt >> 1) & 1);
        __syncthreads();
        if (kt < 7 && tid < 192) {
            int ns = (kt + 1) & 1;
            unsigned nbar = barb + 8 * ns;
            mbar_expect_tx(nbar, 512);
            bulk_cp(dstBase + ns * myStageOff, srcRow + (kt + 1) * 128, 512, nbar);
        }
#pragma unroll
        for (int ks = 0; ks < 16; ks++) {
            wmma::fragment<wmma::matrix_a, 16, 16, 8, wmma::precision::tf32, wmma::row_major> af[2];
            wmma::fragment<wmma::matrix_b, 16, 16, 8, wmma::precision::tf32, wmma::col_major> bf[2];
#pragma unroll
            for (int i = 0; i < 2; i++)
                wmma::load_matrix_sync(af[i], As + st * 64 * 132 + (wm * 32 + i * 16) * 132 + ks * 8,
                                       132);
#pragma unroll
            for (int j = 0; j < 2; j++)
                wmma::load_matrix_sync(bf[j],
                                       Bs + st * 128 * 132 + (wn * 32 + j * 16) * 132 + ks * 8, 132);
#pragma unroll
            for (int i = 0; i < 2; i++)
#pragma unroll
                for (int j = 0; j < 2; j++) wmma::mma_sync(cf[i][j], af[i], bf[j], cf[i][j]);
        }
    }
    __syncthreads();
#pragma unroll
    for (int i = 0; i < 2; i++)
#pragma unroll
        for (int j = 0; j < 2; j++)
            wmma::store_matrix_sync(gbuf + (wm * 32 + i * 16) * 132 + wn * 32 + j * 16, cf[i][j],
                                    132, wmma::mem_row_major);
    __syncthreads();

#pragma unroll
    for (int p = 0; p < 8; p++) {
        int idx = p * 256 + tid;
        int m = idx >> 5, jj = idx & 31;
        int b = m0 + m, j = j0 + jj;
        float ip = gbuf[m * 132 + jj]      + gpre[p][0] + bsum[p][0];
        float fp = gbuf[m * 132 + 32 + jj] + gpre[p][1] + bsum[p][1];
        float gp = gbuf[m * 132 + 64 + jj] + gpre[p][2] + bsum[p][2];
        float op = gbuf[m * 132 + 96 + jj] + gpre[p][3] + bsum[p][3];
        float cn = sigm(fp) * cpre[p] + sigm(ip) * tanhf(gp);
        d_cc[(size_t)b * H2D + j] = cn;
        float hn = sigm(op) * tanhf(cn);
        hnext[(size_t)b * H2D + j] = t32(hn);
        if (t == SLEN - 1) d_hcfull[(size_t)b * H2D + j] = hn;
    }
}

// ---------------- head: 3xTF32 error-compensated GEMM (fp32-accurate) ----------------
__global__ void __launch_bounds__(256) head3_kernel(const float* __restrict__ A,
                                                    const float* __restrict__ W,
                                                    float* __restrict__ C) {
    extern __shared__ float sm[];
    float(*Ahi)[36] = (float(*)[36])sm;
    float(*Alo)[36] = (float(*)[36])(sm + 128 * 36);
    float(*Bhi)[36] = (float(*)[36])(sm + 2 * 128 * 36);
    float(*Blo)[36] = (float(*)[36])(sm + 3 * 128 * 36);
    const int K = H2D, N = VDIM;
    const int m0 = blockIdx.y * 128, n0 = blockIdx.x * 128;
    const int tid = threadIdx.x;
    const int w = tid >> 5, wm = w >> 1, wn = w & 1;

    wmma::fragment<wmma::accumulator, 16, 16, 8, float> cf[2][4];
#pragma unroll
    for (int i = 0; i < 2; i++)
#pragma unroll
        for (int j = 0; j < 4; j++) wmma::fill_fragment(cf[i][j], 0.f);

    for (int k0 = 0; k0 < K; k0 += 32) {
#pragma unroll
        for (int i = 0; i < 4; i++) {
            int lin = tid + i * 256;
            int r = lin >> 3, c4 = (lin & 7) * 4;
            float4 v = *(const float4*)(A + (size_t)(m0 + r) * K + k0 + c4);
            float4 hi, lo;
            hi.x = t32(v.x); lo.x = t32(v.x - hi.x);
            hi.y = t32(v.y); lo.y = t32(v.y - hi.y);
            hi.z = t32(v.z); lo.z = t32(v.z - hi.z);
            hi.w = t32(v.w); lo.w = t32(v.w - hi.w);
            *(float4*)(&Ahi[r][c4]) = hi;
            *(float4*)(&Alo[r][c4]) = lo;
        }
#pragma unroll
        for (int i = 0; i < 4; i++) {
            int lin = tid + i * 256;
            int r = lin >> 3, c4 = (lin & 7) * 4;
            float4 v = *(const float4*)(W + (size_t)(n0 + r) * K + k0 + c4);
            float4 hi, lo;
            hi.x = t32(v.x); lo.x = t32(v.x - hi.x);
            hi.y = t32(v.y); lo.y = t32(v.y - hi.y);
            hi.z = t32(v.z); lo.z = t32(v.z - hi.z);
            hi.w = t32(v.w); lo.w = t32(v.w - hi.w);
            *(float4*)(&Bhi[r][c4]) = hi;
            *(float4*)(&Blo[r][c4]) = lo;
        }
        __syncthreads();
#pragma unroll
        for (int ks = 0; ks < 4; ks++) {
            wmma::fragment<wmma::matrix_a, 16, 16, 8, wmma::precision::tf32, wmma::row_major> ah[2], al[2];
            wmma::fragment<wmma::matrix_b, 16, 16, 8, wmma::precision::tf32, wmma::col_major> bhf[4], blf[4];
#pragma unroll
            for (int i = 0; i < 2; i++) {
                wmma::load_matrix_sync(ah[i], &Ahi[wm * 32 + i * 16][ks * 8], 36);
                wmma::load_matrix_sync(al[i], &Alo[wm * 32 + i * 16][ks * 8], 36);
            }
#pragma unroll
            for (int j = 0; j < 4; j++) {
                wmma::load_matrix_sync(bhf[j], &Bhi[wn * 64 + j * 16][ks * 8], 36);
                wmma::load_matrix_sync(blf[j], &Blo[wn * 64 + j * 16][ks * 8], 36);
            }
#pragma unroll
            for (int i = 0; i < 2; i++)
#pragma unroll
                for (int j = 0; j < 4; j++) {
                    wmma::mma_sync(cf[i][j], al[i], bhf[j], cf[i][j]);
                    wmma::mma_sync(cf[i][j], ah[i], blf[j], cf[i][j]);
                    wmma::mma_sync(cf[i][j], ah[i], bhf[j], cf[i][j]);
                }
        }
        __syncthreads();
    }
#pragma unroll
    for (int i = 0; i < 2; i++)
#pragma unroll
        for (int j = 0; j < 4; j++)
            wmma::store_matrix_sync(C + (size_t)(m0 + wm * 32 + i * 16) * N + n0 + wn * 64 + j * 16,
                                    cf[i][j], N, wmma::mem_row_major);
}

__global__ void bias_add_kernel(float* __restrict__ C, const float* __restrict__ bout) {
    size_t idx = (size_t)blockIdx.x * 256 + threadIdx.x;
    float4 v = ((float4*)C)[idx];
    int n = (int)(idx % (VDIM / 4)) * 4;
    v.x += bout[n]; v.y += bout[n + 1]; v.z += bout[n + 2]; v.w += bout[n + 3];
    ((float4*)C)[idx] = v;
}

// ---------------- host orchestration (single stream) ----------------
extern "C" void kernel_launch(void* const* d_in, const int* in_sizes, int n_in,
                              void* d_out, int out_size) {
    (void)in_sizes; (void)n_in; (void)out_size;
    const int* x = (const int*)d_in[0];
    const float* Wemb = (const float*)d_in[1];
    const float* WihF = (const float*)d_in[2];
    const float* WhhF = (const float*)d_in[3];
    const float* biF = (const float*)d_in[4];
    const float* bhF = (const float*)d_in[5];
    const float* WihB = (const float*)d_in[6];
    const float* WhhB = (const float*)d_in[7];
    const float* biB = (const float*)d_in[8];
    const float* bhB = (const float*)d_in[9];
    const float* WihC = (const float*)d_in[10];
    const float* WhhC = (const float*)d_in[11];
    const float* biC = (const float*)d_in[12];
    const float* bhC = (const float*)d_in[13];
    const float* Wout = (const float*)d_in[14];
    const float* bout = (const float*)d_in[15];
    const float* h0f = (const float*)d_in[16];
    const float* c0f = (const float*)d_in[17];
    const float* h0b = (const float*)d_in[18];
    const float* c0b = (const float*)d_in[19];
    const float* h0c = (const float*)d_in[20];
    const float* c0c = (const float*)d_in[21];
    float* out = (float*)d_out;

    void *pE, *pGf, *pGb, *pCI, *pGc, *phcf;
    void *pWiF, *pWiB, *pWiC, *pWhF, *pWhB, *pWhC;
    cudaGetSymbolAddress(&pE, d_E);
    cudaGetSymbolAddress(&pGf, d_Gf);
    cudaGetSymbolAddress(&pGb, d_Gb);
    cudaGetSymbolAddress(&pCI, d_CombIn);
    cudaGetSymbolAddress(&pGc, d_Gc);
    cudaGetSymbolAddress(&phcf, d_hcfull);
    cudaGetSymbolAddress(&pWiF, d_WihFr);
    cudaGetSymbolAddress(&pWiB, d_WihBr);
    cudaGetSymbolAddress(&pWiC, d_WihCr);
    cudaGetSymbolAddress(&pWhF, d_WhhFr);
    cudaGetSymbolAddress(&pWhB, d_WhhBr);
    cudaGetSymbolAddress(&pWhC, d_WhhCr);

    cudaFuncSetAttribute(gemm_pre, cudaFuncAttributeMaxDynamicSharedMemorySize, 73728);
    cudaFuncSetAttribute(head3_kernel, cudaFuncAttributeMaxDynamicSharedMemorySize, 73728);
    cudaFuncSetAttribute(lstm_step_fb, cudaFuncAttributeMaxDynamicSharedMemorySize, STEP_SMEM);
    cudaFuncSetAttribute(lstm_step_c, cudaFuncAttributeMaxDynamicSharedMemorySize, STEP_SMEM);

    // launch 0: fused prep; launch 1: embedding
    prep_kernel<<<13312, 256>>>(WihF, WihB, WhhF, WhhB, WihC, WhhC,
                                h0f, h0b, h0c, c0f, c0b, c0c);
    embed_kernel<<<NROWS, 128>>>(x, Wemb);
    // input projections: G[sample][4H] = E @ Wih^T
    gemm_pre<<<dim3((4 * HDIM) / 128, NROWS / 128), 256, 73728>>>(
        (const float*)pE, (const float*)pWiF, (float*)pGf, NROWS, 4 * HDIM, HDIM);
    gemm_pre<<<dim3((4 * HDIM) / 128, NROWS / 128), 256, 73728>>>(
        (const float*)pE, (const float*)pWiB, (float*)pGb, NROWS, 4 * HDIM, HDIM);
    // fwd + bwd recurrence, bulk-copy step kernels (1 wave of 128 blocks each)
    for (int t = 0; t < SLEN; t++)
        lstm_step_fb<<<dim3(BSZ / 64, HDIM / 32, 2), 256, STEP_SMEM>>>(
            (const float*)pWhF, (const float*)pWhB, biF, bhF, biB, bhB, t);
    // combiner input projection + recurrence
    gemm_pre<<<dim3((4 * H2D) / 128, NROWS / 128), 256, 73728>>>(
        (const float*)pCI, (const float*)pWiC, (float*)pGc, NROWS, 4 * H2D, H2D);
    for (int t = 0; t < SLEN; t++)
        lstm_step_c<<<dim3(BSZ / 64, H2D / 32), 256, STEP_SMEM>>>(
            (const float*)pWhC, biC, bhC, t);
    // output head (3xTF32) + bias
    head3_kernel<<<dim3(VDIM / 128, BSZ / 128), 256, 73728>>>((const float*)phcf, Wout, out);
    bias_add_kernel<<<(BSZ * VDIM / 4) / 256, 256>>>(out, bout);
}

// round 15
// speedup vs baseline: 1.3737x; 1.0099x over previous
#include <cuda_runtime.h>
#include <mma.h>

using namespace nvcuda;

#define BSZ 256
#define SLEN 64
#define HDIM 512
#define H2D 1024
#define VDIM 32000
#define NROWS (BSZ * SLEN) /* 16384 */

// ---------------- device scratch (static, no allocations) ----------------
__device__ float d_E[(size_t)NROWS * HDIM];         // embeddings (tf32-rounded)
__device__ float d_Gf[(size_t)NROWS * 4 * HDIM];    // fwd input preacts [sample][2048]
__device__ float d_Gb[(size_t)NROWS * 4 * HDIM];    // bwd input preacts
__device__ float d_CombIn[(size_t)NROWS * H2D];     // [hf | hb] per (t,b), rounded
__device__ float d_Gc[(size_t)NROWS * 4 * H2D];     // combiner input preacts [sample][4096]
__device__ float d_h[2][2][BSZ * HDIM];             // [dir][parity], rounded
__device__ float d_cfb[2][BSZ * HDIM];              // [dir], fp32
__device__ float d_hcb[2][BSZ * H2D];               // combiner h [parity], rounded
__device__ float d_cc[BSZ * H2D];                   // fp32
__device__ float d_hcfull[BSZ * H2D];               // final combiner h, FULL fp32 (head input)
__device__ float d_WihFr[4 * HDIM * HDIM];          // tf32-rounded weight copies
__device__ float d_WihBr[4 * HDIM * HDIM];
__device__ float d_WihCr[(size_t)4 * H2D * H2D];
__device__ float d_WhhFr[4 * HDIM * HDIM];
__device__ float d_WhhBr[4 * HDIM * HDIM];
__device__ float d_WhhCr[(size_t)4 * H2D * H2D];

// round-to-nearest-even into tf32 (10 explicit mantissa bits)
__device__ __forceinline__ float t32(float x) {
    unsigned u = __float_as_uint(x);
    unsigned r = (u + 0xFFFu + ((u >> 13) & 1u)) & 0xFFFFE000u;
    return __uint_as_float(r);
}
__device__ __forceinline__ float sigm(float x) { return 1.f / (1.f + __expf(-x)); }

__device__ __forceinline__ void cp16(void* dst, const void* src) {
    unsigned d = (unsigned)__cvta_generic_to_shared(dst);
    asm volatile("cp.async.cg.shared.global [%0], [%1], 16;" ::"r"(d), "l"(src));
}
__device__ __forceinline__ void cp_commit() { asm volatile("cp.async.commit_group;"); }
template <int N>
__device__ __forceinline__ void cp_wait() { asm volatile("cp.async.wait_group %0;" ::"n"(N)); }

// ---- mbarrier + bulk-copy helpers (sm_90+; valid on sm_103a) ----
__device__ __forceinline__ void mbar_init(unsigned bar, unsigned cnt) {
    asm volatile("mbarrier.init.shared.b64 [%0], %1;" ::"r"(bar), "r"(cnt) : "memory");
}
__device__ __forceinline__ void mbar_expect_tx(unsigned bar, unsigned bytes) {
    asm volatile("mbarrier.arrive.expect_tx.shared.b64 _, [%0], %1;" ::"r"(bar), "r"(bytes)
                 : "memory");
}
__device__ __forceinline__ void bulk_cp(unsigned dst, const void* src, unsigned bytes,
                                        unsigned bar) {
    asm volatile(
        "cp.async.bulk.shared::cta.global.mbarrier::complete_tx::bytes [%0], [%1], %2, [%3];"
        ::"r"(dst), "l"(src), "r"(bytes), "r"(bar)
        : "memory");
}
__device__ __forceinline__ void mbar_wait(unsigned bar, unsigned parity) {
    asm volatile(
        "{\n\t"
        ".reg .pred P1;\n\t"
        "WAIT_LOOP_%=:\n\t"
        "mbarrier.try_wait.parity.acquire.cta.shared::cta.b64 P1, [%0], %1, 0x989680;\n\t"
        "@P1 bra.uni WAIT_DONE_%=;\n\t"
        "bra.uni WAIT_LOOP_%=;\n\t"
        "WAIT_DONE_%=:\n\t"
        "}"
        ::"r"(bar), "r"(parity)
        : "memory");
}

// ---------------- fused prep: all weight roundings + state inits in ONE launch ------------
__global__ void __launch_bounds__(256) prep_kernel(
    const float* __restrict__ WihF, const float* __restrict__ WihB,
    const float* __restrict__ WhhF, const float* __restrict__ WhhB,
    const float* __restrict__ WihC, const float* __restrict__ WhhC,
    const float* __restrict__ h0f, const float* __restrict__ h0b, const float* __restrict__ h0c,
    const float* __restrict__ c0f, const float* __restrict__ c0b, const float* __restrict__ c0c) {
    int blk = blockIdx.x;
    const float* src;
    float* dst;
    int base;
    bool doround = true;
    if (blk < 1024)        { src = WihF; dst = d_WihFr; base = blk; }
    else if (blk < 2048)   { src = WihB; dst = d_WihBr; base = blk - 1024; }
    else if (blk < 3072)   { src = WhhF; dst = d_WhhFr; base = blk - 2048; }
    else if (blk < 4096)   { src = WhhB; dst = d_WhhBr; base = blk - 3072; }
    else if (blk < 8192)   { src = WihC; dst = d_WihCr; base = blk - 4096; }
    else if (blk < 12288)  { src = WhhC; dst = d_WhhCr; base = blk - 8192; }
    else if (blk < 12416)  { src = h0f; dst = d_h[0][0]; base = blk - 12288; }
    else if (blk < 12544)  { src = h0b; dst = d_h[1][0]; base = blk - 12416; }
    else if (blk < 12800)  { src = h0c; dst = d_hcb[0]; base = blk - 12544; }
    else if (blk < 12928)  { src = c0f; dst = d_cfb[0]; base = blk - 12800; doround = false; }
    else if (blk < 13056)  { src = c0b; dst = d_cfb[1]; base = blk - 12928; doround = false; }
    else                   { src = c0c; dst = d_cc;     base = blk - 13056; doround = false; }
    size_t i = (size_t)base * 256 + threadIdx.x;
    float4 v = ((const float4*)src)[i];
    if (doround) { v.x = t32(v.x); v.y = t32(v.y); v.z = t32(v.z); v.w = t32(v.w); }
    ((float4*)dst)[i] = v;
}

__global__ void embed_kernel(const int* __restrict__ x, const float* __restrict__ Wemb) {
    int r = blockIdx.x;
    int tok = x[r];
    float4* dst = (float4*)(d_E + (size_t)r * HDIM);
    if (tok == 0) {
        float4 z = {0.f, 0.f, 0.f, 0.f};
        dst[threadIdx.x] = z;
    } else {
        float4 v = ((const float4*)(Wemb + (size_t)tok * HDIM))[threadIdx.x];
        v.x = t32(v.x); v.y = t32(v.y); v.z = t32(v.z); v.w = t32(v.w);
        dst[threadIdx.x] = v;
    }
}

// ---------------- TF32 GEMM, 128x256 block tile, warp tile 64x64, BK=32 ----------------
// C[M,N] = A[M,K] @ W[N,K]^T. 256 threads (8 warps as 2m x 4n). Double-buffered cp.async.
// Fragment loads per MMA: 0.5 (vs 0.75 at 32x64) -> higher tensor utilization.
// smem: As[2][128][36] + Bs[2][256][36] = 110592 B -> 1 CTA/SM.
__global__ void __launch_bounds__(256) gemm_pre(const float* __restrict__ A,
                                                const float* __restrict__ W,
                                                float* __restrict__ C,
                                                int M, int N, int K) {
    extern __shared__ float sm[];
    float* As = sm;                 // [2][128][36]
    float* Bs = sm + 2 * 128 * 36;  // [2][256][36]
    const int m0 = blockIdx.y * 128, n0 = blockIdx.x * 256;
    const int tid = threadIdx.x;
    const int w = tid >> 5, wm = w >> 2, wn = w & 3;
    const int KT = K >> 5;

    wmma::fragment<wmma::accumulator, 16, 16, 8, float> cf[4][4];
#pragma unroll
    for (int i = 0; i < 4; i++)
#pragma unroll
        for (int j = 0; j < 4; j++) wmma::fill_fragment(cf[i][j], 0.f);

    {
#pragma unroll
        for (int i = 0; i < 4; i++) {  // A: 128x32 = 1024 float4
            int lin = tid + i * 256;
            int r = lin >> 3, c4 = (lin & 7) * 4;
            cp16(As + r * 36 + c4, A + (size_t)(m0 + r) * K + c4);
        }
#pragma unroll
        for (int i = 0; i < 8; i++) {  // B: 256x32 = 2048 float4
            int lin = tid + i * 256;
            int r = lin >> 3, c4 = (lin & 7) * 4;
            cp16(Bs + r * 36 + c4, W + (size_t)(n0 + r) * K + c4);
        }
        cp_commit();
    }
    int buf = 0;
#pragma unroll 1
    for (int kt = 0; kt < KT; kt++) {
        cp_wait<0>();
        __syncthreads();
        if (kt + 1 < KT) {
            int nb = buf ^ 1;
#pragma unroll
            for (int i = 0; i < 4; i++) {
                int lin = tid + i * 256;
                int r = lin >> 3, c4 = (lin & 7) * 4;
                cp16(As + nb * 4608 + r * 36 + c4, A + (size_t)(m0 + r) * K + (kt + 1) * 32 + c4);
            }
#pragma unroll
            for (int i = 0; i < 8; i++) {
                int lin = tid + i * 256;
                int r = lin >> 3, c4 = (lin & 7) * 4;
                cp16(Bs + nb * 9216 + r * 36 + c4, W + (size_t)(n0 + r) * K + (kt + 1) * 32 + c4);
            }
            cp_commit();
        }
#pragma unroll
        for (int ks = 0; ks < 4; ks++) {
            wmma::fragment<wmma::matrix_a, 16, 16, 8, wmma::precision::tf32, wmma::row_major> af[4];
            wmma::fragment<wmma::matrix_b, 16, 16, 8, wmma::precision::tf32, wmma::col_major> bf[4];
#pragma unroll
            for (int i = 0; i < 4; i++)
                wmma::load_matrix_sync(af[i], As + buf * 4608 + (wm * 64 + i * 16) * 36 + ks * 8, 36);
#pragma unroll
            for (int j = 0; j < 4; j++)
                wmma::load_matrix_sync(bf[j], Bs + buf * 9216 + (wn * 64 + j * 16) * 36 + ks * 8, 36);
#pragma unroll
            for (int i = 0; i < 4; i++)
#pragma unroll
                for (int j = 0; j < 4; j++) wmma::mma_sync(cf[i][j], af[i], bf[j], cf[i][j]);
        }
        buf ^= 1;
    }
#pragma unroll
    for (int i = 0; i < 4; i++)
#pragma unroll
        for (int j = 0; j < 4; j++)
            wmma::store_matrix_sync(C + (size_t)(m0 + wm * 64 + i * 16) * N + n0 + wn * 64 + j * 16,
                                    cf[i][j], N, wmma::mem_row_major);
}

// ---------------- LSTM step fwd+bwd: BULK-COPY pipeline, BK=128, M=64 tile ----------------
// grid (4, 16, 2) = 128 blocks (1 wave). 256 threads, warps 2(m) x 4(n), cf[2][2].
// smem: As[2][64][132] + Bs[2][128][132] + 2 mbarriers = 202768 B  (1 CTA/SM)
#define STEP_SMEM (2 * 64 * 132 * 4 + 2 * 128 * 132 * 4 + 16)
__global__ void __launch_bounds__(256) lstm_step_fb(
    const float* __restrict__ WhhF, const float* __restrict__ WhhB,
    const float* __restrict__ biF, const float* __restrict__ bhF,
    const float* __restrict__ biB, const float* __restrict__ bhB, int t) {
    extern __shared__ float sm[];
    float* As = sm;                    // [2][64][132]
    float* Bs = sm + 2 * 64 * 132;     // [2][128][132]
    float* gbuf = sm;                  // overlay [64][132] (== As stage 0)
    const unsigned smb = (unsigned)__cvta_generic_to_shared(sm);
    const unsigned barb = smb + (2 * 64 * 132 + 2 * 128 * 132) * 4;

    const int dir = blockIdx.z;
    const float* Whh = dir ? WhhB : WhhF;
    const float* bi = dir ? biB : biF;
    const float* bh = dir ? bhB : bhF;
    const float* hprev = d_h[dir][t & 1];
    float* hnext = d_h[dir][(t + 1) & 1];
    float* cst = d_cfb[dir];
    const float* G = dir ? d_Gb : d_Gf;
    const int grow0 = (dir ? (SLEN - 1 - t) : t) * BSZ;

    const int m0 = blockIdx.x * 64;
    const int j0 = blockIdx.y * 32;
    const int tid = threadIdx.x;
    const int w = tid >> 5, wm = w >> 2, wn = w & 3;

    // hoisted epilogue operand loads (overlap with pipeline below)
    float gpre[8][4], cpre[8], bsum[8][4];
#pragma unroll
    for (int p = 0; p < 8; p++) {
        int idx = p * 256 + tid;
        int m = idx >> 5, jj = idx & 31;
        int b = m0 + m, j = j0 + jj;
        const float* grow = G + (size_t)(grow0 + b) * (4 * HDIM);
        gpre[p][0] = grow[j];
        gpre[p][1] = grow[HDIM + j];
        gpre[p][2] = grow[2 * HDIM + j];
        gpre[p][3] = grow[3 * HDIM + j];
        cpre[p] = cst[(size_t)b * HDIM + j];
        bsum[p][0] = bi[j] + bh[j];
        bsum[p][1] = bi[HDIM + j] + bh[HDIM + j];
        bsum[p][2] = bi[2 * HDIM + j] + bh[2 * HDIM + j];
        bsum[p][3] = bi[3 * HDIM + j] + bh[3 * HDIM + j];
    }

    if (tid == 0) {
        mbar_init(barb, 192);
        mbar_init(barb + 8, 192);
    }
    __syncthreads();

    const float* srcRow = nullptr;
    unsigned dstBase = 0;
    if (tid < 128) {  // B row
        int gr = (tid >> 5) * HDIM + j0 + (tid & 31);
        srcRow = Whh + (size_t)gr * HDIM;
        dstBase = smb + (2 * 64 * 132 + tid * 132) * 4;
    } else if (tid < 192) {  // A row
        int r = tid - 128;
        srcRow = hprev + (size_t)(m0 + r) * HDIM;
        dstBase = smb + (r * 132) * 4;
    }
    const unsigned stageOffB = 128 * 132 * 4;
    const unsigned stageOffA = 64 * 132 * 4;
    const unsigned myStageOff = (tid < 128) ? stageOffB : stageOffA;

    wmma::fragment<wmma::accumulator, 16, 16, 8, float> cf[2][2];
#pragma unroll
    for (int i = 0; i < 2; i++)
#pragma unroll
        for (int j = 0; j < 2; j++) wmma::fill_fragment(cf[i][j], 0.f);

    if (tid < 192) {
        mbar_expect_tx(barb, 512);
        bulk_cp(dstBase, srcRow, 512, barb);
    }
#pragma unroll 1
    for (int kt = 0; kt < 4; kt++) {  // K = 512, BK = 128
        int st = kt & 1;
        mbar_wait(barb + 8 * st, (kt >> 1) & 1);
        __syncthreads();
        if (kt < 3 && tid < 192) {
            int ns = (kt + 1) & 1;
            unsigned nbar = barb + 8 * ns;
            mbar_expect_tx(nbar, 512);
            bulk_cp(dstBase + ns * myStageOff, srcRow + (kt + 1) * 128, 512, nbar);
        }
#pragma unroll
        for (int ks = 0; ks < 16; ks++) {
            wmma::fragment<wmma::matrix_a, 16, 16, 8, wmma::precision::tf32, wmma::row_major> af[2];
            wmma::fragment<wmma::matrix_b, 16, 16, 8, wmma::precision::tf32, wmma::col_major> bf[2];
#pragma unroll
            for (int i = 0; i < 2; i++)
                wmma::load_matrix_sync(af[i], As + st * 64 * 132 + (wm * 32 + i * 16) * 132 + ks * 8,
                                       132);
#pragma unroll
            for (int j = 0; j < 2; j++)
                wmma::load_matrix_sync(bf[j],
                                       Bs + st * 128 * 132 + (wn * 32 + j * 16) * 132 + ks * 8, 132);
#pragma unroll
            for (int i = 0; i < 2; i++)
#pragma unroll
                for (int j = 0; j < 2; j++) wmma::mma_sync(cf[i][j], af[i], bf[j], cf[i][j]);
        }
    }
    __syncthreads();
#pragma unroll
    for (int i = 0; i < 2; i++)
#pragma unroll
        for (int j = 0; j < 2; j++)
            wmma::store_matrix_sync(gbuf + (wm * 32 + i * 16) * 132 + wn * 32 + j * 16, cf[i][j],
                                    132, wmma::mem_row_major);
    __syncthreads();

#pragma unroll
    for (int p = 0; p < 8; p++) {  // 64x32 cell elements
        int idx = p * 256 + tid;
        int m = idx >> 5, jj = idx & 31;
        int b = m0 + m, j = j0 + jj;
        float ip = gbuf[m * 132 + jj]      + gpre[p][0] + bsum[p][0];
        float fp = gbuf[m * 132 + 32 + jj] + gpre[p][1] + bsum[p][1];
        float gp = gbuf[m * 132 + 64 + jj] + gpre[p][2] + bsum[p][2];
        float op = gbuf[m * 132 + 96 + jj] + gpre[p][3] + bsum[p][3];
        float cn = sigm(fp) * cpre[p] + sigm(ip) * tanhf(gp);
        cst[(size_t)b * HDIM + j] = cn;
        float hr = t32(sigm(op) * tanhf(cn));
        hnext[(size_t)b * HDIM + j] = hr;
        d_CombIn[(size_t)(t * BSZ + b) * H2D + dir * HDIM + j] = hr;
    }
}

// ---------------- combiner LSTM step (H=1024): BULK-COPY pipeline, BK=128, M=64 ----------
// grid (4, 32) = 128 blocks (1 wave).
__global__ void __launch_bounds__(256) lstm_step_c(
    const float* __restrict__ Whh, const float* __restrict__ bi,
    const float* __restrict__ bh, int t) {
    extern __shared__ float sm[];
    float* As = sm;
    float* Bs = sm + 2 * 64 * 132;
    float* gbuf = sm;
    const unsigned smb = (unsigned)__cvta_generic_to_shared(sm);
    const unsigned barb = smb + (2 * 64 * 132 + 2 * 128 * 132) * 4;

    const float* hprev = d_hcb[t & 1];
    float* hnext = d_hcb[(t + 1) & 1];
    const int grow0 = t * BSZ;

    const int m0 = blockIdx.x * 64;
    const int j0 = blockIdx.y * 32;
    const int tid = threadIdx.x;
    const int w = tid >> 5, wm = w >> 2, wn = w & 3;

    float gpre[8][4], cpre[8], bsum[8][4];
#pragma unroll
    for (int p = 0; p < 8; p++) {
        int idx = p * 256 + tid;
        int m = idx >> 5, jj = idx & 31;
        int b = m0 + m, j = j0 + jj;
        const float* grow = d_Gc + (size_t)(grow0 + b) * (4 * H2D);
        gpre[p][0] = grow[j];
        gpre[p][1] = grow[H2D + j];
        gpre[p][2] = grow[2 * H2D + j];
        gpre[p][3] = grow[3 * H2D + j];
        cpre[p] = d_cc[(size_t)b * H2D + j];
        bsum[p][0] = bi[j] + bh[j];
        bsum[p][1] = bi[H2D + j] + bh[H2D + j];
        bsum[p][2] = bi[2 * H2D + j] + bh[2 * H2D + j];
        bsum[p][3] = bi[3 * H2D + j] + bh[3 * H2D + j];
    }

    if (tid == 0) {
        mbar_init(barb, 192);
        mbar_init(barb + 8, 192);
    }
    __syncthreads();

    const float* srcRow = nullptr;
    unsigned dstBase = 0;
    if (tid < 128) {
        int gr = (tid >> 5) * H2D + j0 + (tid & 31);
        srcRow = Whh + (size_t)gr * H2D;
        dstBase = smb + (2 * 64 * 132 + tid * 132) * 4;
    } else if (tid < 192) {
        int r = tid - 128;
        srcRow = hprev + (size_t)(m0 + r) * H2D;
        dstBase = smb + (r * 132) * 4;
    }
    const unsigned stageOffB = 128 * 132 * 4;
    const unsigned stageOffA = 64 * 132 * 4;
    const unsigned myStageOff = (tid < 128) ? stageOffB : stageOffA;

    wmma::fragment<wmma::accumulator, 16, 16, 8, float> cf[2][2];
#pragma unroll
    for (int i = 0; i < 2; i++)
#pragma unroll
        for (int j = 0; j < 2; j++) wmma::fill_fragment(cf[i][j], 0.f);

    if (tid < 192) {
        mbar_expect_tx(barb, 512);
        bulk_cp(dstBase, srcRow, 512, barb);
    }
#pragma unroll 1
    for (int kt = 0; kt < 8; kt++) {  // K = 1024, BK = 128
        int st = kt & 1;
        mbar_wait(barb + 8 * st, (kt >> 1) & 1);
        __syncthreads();
        if (kt < 7 && tid < 192) {
            int ns = (kt + 1) & 1;
            unsigned nbar = barb + 8 * ns;
            mbar_expect_tx(nbar, 512);
            bulk_cp(dstBase + ns * myStageOff, srcRow + (kt + 1) * 128, 512, nbar);
        }
#pragma unroll
        for (int ks = 0; ks < 16; ks++) {
            wmma::fragment<wmma::matrix_a, 16, 16, 8, wmma::precision::tf32, wmma::row_major> af[2];
            wmma::fragment<wmma::matrix_b, 16, 16, 8, wmma::precision::tf32, wmma::col_major> bf[2];
#pragma unroll
            for (int i = 0; i < 2; i++)
                wmma::load_matrix_sync(af[i], As + st * 64 * 132 + (wm * 32 + i * 16) * 132 + ks * 8,
                                       132);
#pragma unroll
            for (int j = 0; j < 2; j++)
                wmma::load_matrix_sync(bf[j],
                                       Bs + st * 128 * 132 + (wn * 32 + j * 16) * 132 + ks * 8, 132);
#pragma unroll
            for (int i = 0; i < 2; i++)
#pragma unroll
                for (int j = 0; j < 2; j++) wmma::mma_sync(cf[i][j], af[i], bf[j], cf[i][j]);
        }
    }
    __syncthreads();
#pragma unroll
    for (int i = 0; i < 2; i++)
#pragma unroll
        for (int j = 0; j < 2; j++)
            wmma::store_matrix_sync(gbuf + (wm * 32 + i * 16) * 132 + wn * 32 + j * 16, cf[i][j],
                                    132, wmma::mem_row_major);
    __syncthreads();

#pragma unroll
    for (int p = 0; p < 8; p++) {
        int idx = p * 256 + tid;
        int m = idx >> 5, jj = idx & 31;
        int b = m0 + m, j = j0 + jj;
        float ip = gbuf[m * 132 + jj]      + gpre[p][0] + bsum[p][0];
        float fp = gbuf[m * 132 + 32 + jj] + gpre[p][1] + bsum[p][1];
        float gp = gbuf[m * 132 + 64 + jj] + gpre[p][2] + bsum[p][2];
        float op = gbuf[m * 132 + 96 + jj] + gpre[p][3] + bsum[p][3];
        float cn = sigm(fp) * cpre[p] + sigm(ip) * tanhf(gp);
        d_cc[(size_t)b * H2D + j] = cn;
        float hn = sigm(op) * tanhf(cn);
        hnext[(size_t)b * H2D + j] = t32(hn);
        if (t == SLEN - 1) d_hcfull[(size_t)b * H2D + j] = hn;
    }
}

// ---------------- head: 3xTF32 error-compensated GEMM (fp32-accurate) ----------------
__global__ void __launch_bounds__(256) head3_kernel(const float* __restrict__ A,
                                                    const float* __restrict__ W,
                                                    float* __restrict__ C) {
    extern __shared__ float sm[];
    float(*Ahi)[36] = (float(*)[36])sm;
    float(*Alo)[36] = (float(*)[36])(sm + 128 * 36);
    float(*Bhi)[36] = (float(*)[36])(sm + 2 * 128 * 36);
    float(*Blo)[36] = (float(*)[36])(sm + 3 * 128 * 36);
    const int K = H2D, N = VDIM;
    const int m0 = blockIdx.y * 128, n0 = blockIdx.x * 128;
    const int tid = threadIdx.x;
    const int w = tid >> 5, wm = w >> 1, wn = w & 1;

    wmma::fragment<wmma::accumulator, 16, 16, 8, float> cf[2][4];
#pragma unroll
    for (int i = 0; i < 2; i++)
#pragma unroll
        for (int j = 0; j < 4; j++) wmma::fill_fragment(cf[i][j], 0.f);

    for (int k0 = 0; k0 < K; k0 += 32) {
#pragma unroll
        for (int i = 0; i < 4; i++) {
            int lin = tid + i * 256;
            int r = lin >> 3, c4 = (lin & 7) * 4;
            float4 v = *(const float4*)(A + (size_t)(m0 + r) * K + k0 + c4);
            float4 hi, lo;
            hi.x = t32(v.x); lo.x = t32(v.x - hi.x);
            hi.y = t32(v.y); lo.y = t32(v.y - hi.y);
            hi.z = t32(v.z); lo.z = t32(v.z - hi.z);
            hi.w = t32(v.w); lo.w = t32(v.w - hi.w);
            *(float4*)(&Ahi[r][c4]) = hi;
            *(float4*)(&Alo[r][c4]) = lo;
        }
#pragma unroll
        for (int i = 0; i < 4; i++) {
            int lin = tid + i * 256;
            int r = lin >> 3, c4 = (lin & 7) * 4;
            float4 v = *(const float4*)(W + (size_t)(n0 + r) * K + k0 + c4);
            float4 hi, lo;
            hi.x = t32(v.x); lo.x = t32(v.x - hi.x);
            hi.y = t32(v.y); lo.y = t32(v.y - hi.y);
            hi.z = t32(v.z); lo.z = t32(v.z - hi.z);
            hi.w = t32(v.w); lo.w = t32(v.w - hi.w);
            *(float4*)(&Bhi[r][c4]) = hi;
            *(float4*)(&Blo[r][c4]) = lo;
        }
        __syncthreads();
#pragma unroll
        for (int ks = 0; ks < 4; ks++) {
            wmma::fragment<wmma::matrix_a, 16, 16, 8, wmma::precision::tf32, wmma::row_major> ah[2], al[2];
            wmma::fragment<wmma::matrix_b, 16, 16, 8, wmma::precision::tf32, wmma::col_major> bhf[4], blf[4];
#pragma unroll
            for (int i = 0; i < 2; i++) {
                wmma::load_matrix_sync(ah[i], &Ahi[wm * 32 + i * 16][ks * 8], 36);
                wmma::load_matrix_sync(al[i], &Alo[wm * 32 + i * 16][ks * 8], 36);
            }
#pragma unroll
            for (int j = 0; j < 4; j++) {
                wmma::load_matrix_sync(bhf[j], &Bhi[wn * 64 + j * 16][ks * 8], 36);
                wmma::load_matrix_sync(blf[j], &Blo[wn * 64 + j * 16][ks * 8], 36);
            }
#pragma unroll
            for (int i = 0; i < 2; i++)
#pragma unroll
                for (int j = 0; j < 4; j++) {
                    wmma::mma_sync(cf[i][j], al[i], bhf[j], cf[i][j]);
                    wmma::mma_sync(cf[i][j], ah[i], blf[j], cf[i][j]);
                    wmma::mma_sync(cf[i][j], ah[i], bhf[j], cf[i][j]);
                }
        }
        __syncthreads();
    }
#pragma unroll
    for (int i = 0; i < 2; i++)
#pragma unroll
        for (int j = 0; j < 4; j++)
            wmma::store_matrix_sync(C + (size_t)(m0 + wm * 32 + i * 16) * N + n0 + wn * 64 + j * 16,
                                    cf[i][j], N, wmma::mem_row_major);
}

__global__ void bias_add_kernel(float* __restrict__ C, const float* __restrict__ bout) {
    size_t idx = (size_t)blockIdx.x * 256 + threadIdx.x;
    float4 v = ((float4*)C)[idx];
    int n = (int)(idx % (VDIM / 4)) * 4;
    v.x += bout[n]; v.y += bout[n + 1]; v.z += bout[n + 2]; v.w += bout[n + 3];
    ((float4*)C)[idx] = v;
}

// ---------------- host orchestration (single stream) ----------------
extern "C" void kernel_launch(void* const* d_in, const int* in_sizes, int n_in,
                              void* d_out, int out_size) {
    (void)in_sizes; (void)n_in; (void)out_size;
    const int* x = (const int*)d_in[0];
    const float* Wemb = (const float*)d_in[1];
    const float* WihF = (const float*)d_in[2];
    const float* WhhF = (const float*)d_in[3];
    const float* biF = (const float*)d_in[4];
    const float* bhF = (const float*)d_in[5];
    const float* WihB = (const float*)d_in[6];
    const float* WhhB = (const float*)d_in[7];
    const float* biB = (const float*)d_in[8];
    const float* bhB = (const float*)d_in[9];
    const float* WihC = (const float*)d_in[10];
    const float* WhhC = (const float*)d_in[11];
    const float* biC = (const float*)d_in[12];
    const float* bhC = (const float*)d_in[13];
    const float* Wout = (const float*)d_in[14];
    const float* bout = (const float*)d_in[15];
    const float* h0f = (const float*)d_in[16];
    const float* c0f = (const float*)d_in[17];
    const float* h0b = (const float*)d_in[18];
    const float* c0b = (const float*)d_in[19];
    const float* h0c = (const float*)d_in[20];
    const float* c0c = (const float*)d_in[21];
    float* out = (float*)d_out;

    void *pE, *pGf, *pGb, *pCI, *pGc, *phcf;
    void *pWiF, *pWiB, *pWiC, *pWhF, *pWhB, *pWhC;
    cudaGetSymbolAddress(&pE, d_E);
    cudaGetSymbolAddress(&pGf, d_Gf);
    cudaGetSymbolAddress(&pGb, d_Gb);
    cudaGetSymbolAddress(&pCI, d_CombIn);
    cudaGetSymbolAddress(&pGc, d_Gc);
    cudaGetSymbolAddress(&phcf, d_hcfull);
    cudaGetSymbolAddress(&pWiF, d_WihFr);
    cudaGetSymbolAddress(&pWiB, d_WihBr);
    cudaGetSymbolAddress(&pWiC, d_WihCr);
    cudaGetSymbolAddress(&pWhF, d_WhhFr);
    cudaGetSymbolAddress(&pWhB, d_WhhBr);
    cudaGetSymbolAddress(&pWhC, d_WhhCr);

    cudaFuncSetAttribute(gemm_pre, cudaFuncAttributeMaxDynamicSharedMemorySize, 110592);
    cudaFuncSetAttribute(head3_kernel, cudaFuncAttributeMaxDynamicSharedMemorySize, 73728);
    cudaFuncSetAttribute(lstm_step_fb, cudaFuncAttributeMaxDynamicSharedMemorySize, STEP_SMEM);
    cudaFuncSetAttribute(lstm_step_c, cudaFuncAttributeMaxDynamicSharedMemorySize, STEP_SMEM);

    // launch 0: fused prep; launch 1: embedding
    prep_kernel<<<13312, 256>>>(WihF, WihB, WhhF, WhhB, WihC, WhhC,
                                h0f, h0b, h0c, c0f, c0b, c0c);
    embed_kernel<<<NROWS, 128>>>(x, Wemb);
    // input projections: G[sample][4H] = E @ Wih^T  (128x256 tiles)
    gemm_pre<<<dim3((4 * HDIM) / 256, NROWS / 128), 256, 110592>>>(
        (const float*)pE, (const float*)pWiF, (float*)pGf, NROWS, 4 * HDIM, HDIM);
    gemm_pre<<<dim3((4 * HDIM) / 256, NROWS / 128), 256, 110592>>>(
        (const float*)pE, (const float*)pWiB, (float*)pGb, NROWS, 4 * HDIM, HDIM);
    // fwd + bwd recurrence, bulk-copy step kernels (1 wave of 128 blocks each)
    for (int t = 0; t < SLEN; t++)
        lstm_step_fb<<<dim3(BSZ / 64, HDIM / 32, 2), 256, STEP_SMEM>>>(
            (const float*)pWhF, (const float*)pWhB, biF, bhF, biB, bhB, t);
    // combiner input projection + recurrence
    gemm_pre<<<dim3((4 * H2D) / 256, NROWS / 128), 256, 110592>>>(
        (const float*)pCI, (const float*)pWiC, (float*)pGc, NROWS, 4 * H2D, H2D);
    for (int t = 0; t < SLEN; t++)
        lstm_step_c<<<dim3(BSZ / 64, H2D / 32), 256, STEP_SMEM>>>(
            (const float*)pWhC, biC, bhC, t);
    // output head (3xTF32) + bias
    head3_kernel<<<dim3(VDIM / 128, BSZ / 128), 256, 73728>>>((const float*)phcf, Wout, out);
    bias_add_kernel<<<(BSZ * VDIM / 4) / 256, 256>>>(out, bout);
}